// round 9
// baseline (speedup 1.0000x reference)
#include <cuda_runtime.h>

#define N_NODES   50000
#define N_REL     10
#define R2        21
#define N_TRIPLES 500000
#define ETOT      (2 * N_TRIPLES + N_NODES)   // 1,050,000 augmented edges
#define BATCH     16384
#define KEYN      (N_NODES * R2)              // keys (src*21+p)
#define SCAN_CHUNK 4096
#define SCAN_NB   ((KEYN + SCAN_CHUNK - 1) / SCAN_CHUNK)   // 257
#define MAXFLAG   32768

// Static scratch (no runtime allocation)
__device__ int   g_colsum[KEYN];
__device__ int   g_keycnt[KEYN];
__device__ int   g_keyoff[KEYN];
__device__ int   g_scanblk[512];
__device__ int   g_sorted[ETOT];
__device__ float g_h[N_NODES * 64];
__device__ float g_nodes[N_NODES * 64];
__device__ int   g_flag[N_NODES];
__device__ int   g_list[N_NODES];
__device__ int   g_cnt[1];
__device__ float g_w1t[R2 * 64 * 64];   // w1 transposed: [p][out_col][k]

__device__ __forceinline__ unsigned long long pack2(float x, float y) {
    unsigned long long r;
    asm("mov.b64 %0, {%1, %2};" : "=l"(r) : "f"(x), "f"(y));
    return r;
}
__device__ __forceinline__ void unpack2(float& x, float& y, unsigned long long v) {
    asm("mov.b64 {%0, %1}, %2;" : "=f"(x), "=f"(y) : "l"(v));
}
__device__ __forceinline__ void ffma2(unsigned long long& acc,
                                      unsigned long long a, unsigned long long b) {
    asm("fma.rn.f32x2 %0, %1, %2, %0;" : "+l"(acc) : "l"(a), "l"(b));
}

__device__ __forceinline__ void decode_edge(int idx, const int* __restrict__ triples,
                                            int& src, int& p, int& o) {
    if (idx < N_TRIPLES) {
        src = triples[3 * idx + 0];
        p   = triples[3 * idx + 1];
        o   = triples[3 * idx + 2];
    } else if (idx < N_TRIPLES + N_NODES) {
        int i = idx - N_TRIPLES;
        src = i; p = 2 * N_REL; o = i;
    } else {
        int e = idx - N_TRIPLES - N_NODES;
        src = triples[3 * e + 2];
        p   = triples[3 * e + 1] + N_REL;
        o   = triples[3 * e + 0];
    }
}

// ---------------------------------------------------------------------------
__global__ void k_init() {
    int idx = blockIdx.x * blockDim.x + threadIdx.x;
    if (idx < KEYN) { g_colsum[idx] = 0; g_keycnt[idx] = 0; }
    if (idx < N_NODES) g_flag[idx] = 0;
    if (idx == 0) g_cnt[0] = 0;
}

// ---------------------------------------------------------------------------
// Transpose w1[p][k][c] -> g_w1t[p][c][k]  (21*4096 elements)
// ---------------------------------------------------------------------------
__global__ void k_transpose(const float* __restrict__ w1) {
    int idx = blockIdx.x * blockDim.x + threadIdx.x;
    if (idx >= R2 * 4096) return;
    int p = idx >> 12, rem = idx & 4095;
    int c = rem >> 6, k = rem & 63;
    g_w1t[idx] = __ldg(w1 + p * 4096 + k * 64 + c);
}

// ---------------------------------------------------------------------------
__global__ void k_hist(const int* __restrict__ triples) {
    int idx = blockIdx.x * blockDim.x + threadIdx.x;
    if (idx >= ETOT) return;
    int src, p, o;
    decode_edge(idx, triples, src, p, o);
    atomicAdd(&g_colsum[p * N_NODES + o], 1);
    atomicAdd(&g_keycnt[src * R2 + p], 1);
}

// ---------------------------------------------------------------------------
// 3-pass exclusive scan of g_keycnt -> g_keyoff
// ---------------------------------------------------------------------------
__global__ void k_scanA() {
    int b = blockIdx.x, tid = threadIdx.x;
    int base = b * SCAN_CHUNK + tid * 16;
    int s = 0;
    #pragma unroll
    for (int j = 0; j < 16; j++) {
        int idx = base + j;
        if (idx < KEYN) s += g_keycnt[idx];
    }
    __shared__ int sh[256];
    sh[tid] = s; __syncthreads();
    for (int off = 128; off; off >>= 1) {
        if (tid < off) sh[tid] += sh[tid + off];
        __syncthreads();
    }
    if (tid == 0) g_scanblk[b] = sh[0];
}

__global__ void k_scanB() {
    int tid = threadIdx.x;              // 512 threads, 1 block
    __shared__ int sh[512];
    int orig = (tid < SCAN_NB) ? g_scanblk[tid] : 0;
    sh[tid] = orig; __syncthreads();
    for (int off = 1; off < 512; off <<= 1) {
        int add = (tid >= off) ? sh[tid - off] : 0;
        __syncthreads();
        sh[tid] += add;
        __syncthreads();
    }
    if (tid < SCAN_NB) g_scanblk[tid] = sh[tid] - orig;   // exclusive
}

__global__ void k_scanC() {
    int b = blockIdx.x, tid = threadIdx.x;
    int base = b * SCAN_CHUNK + tid * 16;
    int v[16];
    #pragma unroll
    for (int j = 0; j < 16; j++) {
        int idx = base + j;
        v[j] = (idx < KEYN) ? g_keycnt[idx] : 0;
    }
    int tot = 0;
    #pragma unroll
    for (int j = 0; j < 16; j++) { int t = v[j]; v[j] = tot; tot += t; }
    __shared__ int sh[256];
    sh[tid] = tot; __syncthreads();
    int orig = tot;
    for (int off = 1; off < 256; off <<= 1) {
        int add = (tid >= off) ? sh[tid - off] : 0;
        __syncthreads();
        sh[tid] += add;
        __syncthreads();
    }
    int texcl = sh[tid] - orig + g_scanblk[b];
    #pragma unroll
    for (int j = 0; j < 16; j++) {
        int idx = base + j;
        if (idx < KEYN) g_keyoff[idx] = texcl + v[j];
    }
}

// ---------------------------------------------------------------------------
// Scatter: after this, g_keyoff[k] = exclusive END of key k
// ---------------------------------------------------------------------------
__global__ void k_scatter(const int* __restrict__ triples) {
    int idx = blockIdx.x * blockDim.x + threadIdx.x;
    if (idx >= ETOT) return;
    int src, p, o;
    decode_edge(idx, triples, src, p, o);
    int pos = atomicAdd(&g_keyoff[src * R2 + p], 1);
    g_sorted[pos] = (p << 16) | o;
}

// ---------------------------------------------------------------------------
// Layer 1: 16-thread group per node, register accumulation, no atomics.
// ---------------------------------------------------------------------------
__global__ void k_layer1(const float* __restrict__ w0, const float* __restrict__ b0) {
    int t = blockIdx.x * blockDim.x + threadIdx.x;
    int u = t >> 4, lane = t & 15;
    if (u >= N_NODES) return;
    int s = (u == 0) ? 0 : g_keyoff[u * R2 - 1];
    int e = g_keyoff[u * R2 + R2 - 1];

    const float4* w0f4 = reinterpret_cast<const float4*>(w0);
    float4 acc = make_float4(0.f, 0.f, 0.f, 0.f);
    for (int i = s; i < e; i++) {
        int packed = g_sorted[i];
        int p = packed >> 16, o = packed & 0xFFFF;
        int col = p * N_NODES + o;
        float val = 1.0f / (float)g_colsum[col];
        float4 w = __ldg(w0f4 + (size_t)col * 16 + lane);
        acc.x = fmaf(val, w.x, acc.x);
        acc.y = fmaf(val, w.y, acc.y);
        acc.z = fmaf(val, w.z, acc.z);
        acc.w = fmaf(val, w.w, acc.w);
    }
    float4 bb = __ldg(reinterpret_cast<const float4*>(b0) + lane);
    float4 r = make_float4(bb.x + acc.x, bb.y + acc.y, bb.z + acc.z, bb.w + acc.w);
    *reinterpret_cast<float4*>(g_h + u * 64 + lane * 4) = r;
}

// ---------------------------------------------------------------------------
__global__ void k_flag(const int* __restrict__ batch) {
    int b = blockIdx.x * blockDim.x + threadIdx.x;
    if (b < BATCH) {
        g_flag[batch[3 * b + 0]] = 1;
        g_flag[batch[3 * b + 2]] = 1;
    }
}

__global__ void k_compact() {
    int u = blockIdx.x * blockDim.x + threadIdx.x;
    if (u < N_NODES && g_flag[u]) {
        int i = atomicAdd(&g_cnt[0], 1);
        g_list[i] = u;
    }
}

// ---------------------------------------------------------------------------
// Layer 2: one warp per flagged node. Edges p-sorted within node: accumulate
// hsum per p-run (float2 over cols 2l,2l+1 == packed k-pair layout), then
// flush via FFMA2 GEMV against transposed w1 (wT[p][c][k], k contiguous).
// Lane owns output cols {lane, lane+32}; accumulators packed over k-parity.
// Per-run flush: 1 STS.64 + 16 LDS.128 + 32 LDG.128 + 64 FFMA2.
// ---------------------------------------------------------------------------
__global__ void k_layer2(const float* __restrict__ b1) {
    int t = blockIdx.x * blockDim.x + threadIdx.x;
    int w = t >> 5, lane = t & 31;
    int wid = threadIdx.x >> 5;
    __shared__ __align__(16) unsigned long long hs[8][32];

    if (w >= g_cnt[0]) return;
    int u = g_list[w];

    int s = (u == 0) ? 0 : g_keyoff[u * R2 - 1];
    int e = g_keyoff[u * R2 + R2 - 1];

    unsigned long long acc0 = 0ull, acc1 = 0ull;   // cols lane, lane+32 (k-parity pairs)
    float2 hacc = make_float2(0.f, 0.f);
    int curp = -1;

    for (int i = s; i <= e; i++) {
        int p = -2, o = 0;
        if (i < e) {
            int pk = g_sorted[i];
            p = pk >> 16; o = pk & 0xFFFF;
        }
        if (p != curp) {
            if (curp >= 0) {
                hs[wid][lane] = pack2(hacc.x, hacc.y);   // (hsum[2l], hsum[2l+1])
                __syncwarp();
                const ulonglong2* W0 = reinterpret_cast<const ulonglong2*>(
                    g_w1t + curp * 4096 + lane * 64);
                const ulonglong2* W1 = reinterpret_cast<const ulonglong2*>(
                    g_w1t + curp * 4096 + (lane + 32) * 64);
                const ulonglong2* H = reinterpret_cast<const ulonglong2*>(hs[wid]);
                #pragma unroll
                for (int j = 0; j < 16; j++) {
                    ulonglong2 hq = H[j];                 // hsum[4j..4j+3] packed
                    ulonglong2 w0q = __ldg(W0 + j);       // wT[c0][4j..4j+3]
                    ffma2(acc0, hq.x, w0q.x);
                    ffma2(acc0, hq.y, w0q.y);
                    ulonglong2 w1q = __ldg(W1 + j);       // wT[c1][4j..4j+3]
                    ffma2(acc1, hq.x, w1q.x);
                    ffma2(acc1, hq.y, w1q.y);
                }
                __syncwarp();
            }
            curp = p;
            hacc = make_float2(0.f, 0.f);
        }
        if (i < e) {
            float val = 1.0f / (float)g_colsum[p * N_NODES + o];
            float2 hv = *reinterpret_cast<const float2*>(g_h + o * 64 + 2 * lane);
            hacc.x = fmaf(val, hv.x, hacc.x);
            hacc.y = fmaf(val, hv.y, hacc.y);
        }
    }

    float lo0, hi0, lo1, hi1;
    unpack2(lo0, hi0, acc0);
    unpack2(lo1, hi1, acc1);
    g_nodes[u * 64 + lane]      = __ldg(b1 + lane)      + lo0 + hi0;
    g_nodes[u * 64 + lane + 32] = __ldg(b1 + lane + 32) + lo1 + hi1;
}

// ---------------------------------------------------------------------------
__global__ void k_score(const int* __restrict__ batch, const float* __restrict__ rel,
                        float* __restrict__ out) {
    int t = blockIdx.x * blockDim.x + threadIdx.x;
    int b = t >> 5, lane = t & 31;
    if (b >= BATCH) return;
    int si = batch[3 * b + 0];
    int pi = batch[3 * b + 1];
    int oi = batch[3 * b + 2];
    const float* ns = g_nodes + si * 64;
    const float* no = g_nodes + oi * 64;
    const float* rr = rel + pi * 64;
    float a = ns[lane]      * rr[lane]      * no[lane]
            + ns[lane + 32] * rr[lane + 32] * no[lane + 32];
    #pragma unroll
    for (int off = 16; off; off >>= 1)
        a += __shfl_xor_sync(0xffffffffu, a, off);
    if (lane == 0) out[b] = a;
}

// ---------------------------------------------------------------------------
extern "C" void kernel_launch(void* const* d_in, const int* in_sizes, int n_in,
                              void* d_out, int out_size) {
    const int*   batch     = (const int*)  d_in[0];
    const int*   triples   = (const int*)  d_in[1];
    const float* w0        = (const float*)d_in[2];
    const float* b0        = (const float*)d_in[3];
    const float* w1        = (const float*)d_in[4];
    const float* b1        = (const float*)d_in[5];
    const float* relations = (const float*)d_in[6];
    float* out = (float*)d_out;

    const int TPB = 256;

    k_init<<<(KEYN + TPB - 1) / TPB, TPB>>>();
    k_transpose<<<(R2 * 4096 + TPB - 1) / TPB, TPB>>>(w1);
    k_hist<<<(ETOT + TPB - 1) / TPB, TPB>>>(triples);
    k_scanA<<<SCAN_NB, 256>>>();
    k_scanB<<<1, 512>>>();
    k_scanC<<<SCAN_NB, 256>>>();
    k_scatter<<<(ETOT + TPB - 1) / TPB, TPB>>>(triples);
    k_layer1<<<(N_NODES * 16 + TPB - 1) / TPB, TPB>>>(w0, b0);
    k_flag<<<(BATCH + TPB - 1) / TPB, TPB>>>(batch);
    k_compact<<<(N_NODES + TPB - 1) / TPB, TPB>>>();
    k_layer2<<<(MAXFLAG * 32 + TPB - 1) / TPB, TPB>>>(b1);
    k_score<<<(BATCH * 32 + TPB - 1) / TPB, TPB>>>(batch, relations, out);
}

// round 10
// speedup vs baseline: 3.7875x; 3.7875x over previous
#include <cuda_runtime.h>

#define N_NODES   50000
#define N_REL     10
#define R2        21
#define N_TRIPLES 500000
#define ETOT      (2 * N_TRIPLES + N_NODES)   // 1,050,000 augmented edges
#define BATCH     16384
#define KEYN      (N_NODES * R2)              // keys (src*21+p)
#define SCAN_CHUNK 4096
#define SCAN_NB   ((KEYN + SCAN_CHUNK - 1) / SCAN_CHUNK)   // 257
#define MAXFLAG   32768

// Static scratch (no runtime allocation)
__device__ int   g_colsum[KEYN];
__device__ int   g_keycnt[KEYN];
__device__ int   g_keyoff[KEYN];
__device__ int   g_scanblk[512];
__device__ int   g_sorted[ETOT];
__device__ float g_h[N_NODES * 64];
__device__ float g_nodes[N_NODES * 64];
__device__ int   g_flag[N_NODES];
__device__ int   g_list[N_NODES];
__device__ int   g_cnt[1];
// Interleaved w1 for FFMA2 flush: [p][k2][lane] ulonglong2 where
//  .x = pack(w1[p][2*k2  ][2*lane], w1[p][2*k2  ][2*lane+1])
//  .y = pack(w1[p][2*k2+1][2*lane], w1[p][2*k2+1][2*lane+1])
__device__ ulonglong2 g_w1i[R2 * 32 * 32];

__device__ __forceinline__ unsigned long long pack2(float x, float y) {
    unsigned long long r;
    asm("mov.b64 %0, {%1, %2};" : "=l"(r) : "f"(x), "f"(y));
    return r;
}
__device__ __forceinline__ unsigned long long dup2(float x) {
    unsigned long long r;
    asm("mov.b64 %0, {%1, %1};" : "=l"(r) : "f"(x));
    return r;
}
__device__ __forceinline__ void unpack2(float& x, float& y, unsigned long long v) {
    asm("mov.b64 {%0, %1}, %2;" : "=f"(x), "=f"(y) : "l"(v));
}
__device__ __forceinline__ void ffma2(unsigned long long& acc,
                                      unsigned long long a, unsigned long long b) {
    asm("fma.rn.f32x2 %0, %1, %2, %0;" : "+l"(acc) : "l"(a), "l"(b));
}

__device__ __forceinline__ void decode_edge(int idx, const int* __restrict__ triples,
                                            int& src, int& p, int& o) {
    if (idx < N_TRIPLES) {
        src = triples[3 * idx + 0];
        p   = triples[3 * idx + 1];
        o   = triples[3 * idx + 2];
    } else if (idx < N_TRIPLES + N_NODES) {
        int i = idx - N_TRIPLES;
        src = i; p = 2 * N_REL; o = i;
    } else {
        int e = idx - N_TRIPLES - N_NODES;
        src = triples[3 * e + 2];
        p   = triples[3 * e + 1] + N_REL;
        o   = triples[3 * e + 0];
    }
}

// ---------------------------------------------------------------------------
__global__ void k_init() {
    int idx = blockIdx.x * blockDim.x + threadIdx.x;
    if (idx < KEYN) { g_colsum[idx] = 0; g_keycnt[idx] = 0; }
    if (idx < N_NODES) g_flag[idx] = 0;
    if (idx == 0) g_cnt[0] = 0;
}

// ---------------------------------------------------------------------------
// Build interleaved w1: one thread per (p, k2, lane) output slot.
// ---------------------------------------------------------------------------
__global__ void k_w1i(const float* __restrict__ w1) {
    int idx = blockIdx.x * blockDim.x + threadIdx.x;
    if (idx >= R2 * 32 * 32) return;
    int p = idx >> 10, rem = idx & 1023;
    int k2 = rem >> 5, lane = rem & 31;
    const float* base = w1 + p * 4096;
    float a0 = __ldg(base + (2 * k2)     * 64 + 2 * lane);
    float a1 = __ldg(base + (2 * k2)     * 64 + 2 * lane + 1);
    float b0 = __ldg(base + (2 * k2 + 1) * 64 + 2 * lane);
    float b1v = __ldg(base + (2 * k2 + 1) * 64 + 2 * lane + 1);
    ulonglong2 v;
    v.x = pack2(a0, a1);
    v.y = pack2(b0, b1v);
    g_w1i[idx] = v;
}

// ---------------------------------------------------------------------------
__global__ void k_hist(const int* __restrict__ triples) {
    int idx = blockIdx.x * blockDim.x + threadIdx.x;
    if (idx >= ETOT) return;
    int src, p, o;
    decode_edge(idx, triples, src, p, o);
    atomicAdd(&g_colsum[p * N_NODES + o], 1);
    atomicAdd(&g_keycnt[src * R2 + p], 1);
}

// ---------------------------------------------------------------------------
// 3-pass exclusive scan of g_keycnt -> g_keyoff
// ---------------------------------------------------------------------------
__global__ void k_scanA() {
    int b = blockIdx.x, tid = threadIdx.x;
    int base = b * SCAN_CHUNK + tid * 16;
    int s = 0;
    #pragma unroll
    for (int j = 0; j < 16; j++) {
        int idx = base + j;
        if (idx < KEYN) s += g_keycnt[idx];
    }
    __shared__ int sh[256];
    sh[tid] = s; __syncthreads();
    for (int off = 128; off; off >>= 1) {
        if (tid < off) sh[tid] += sh[tid + off];
        __syncthreads();
    }
    if (tid == 0) g_scanblk[b] = sh[0];
}

__global__ void k_scanB() {
    int tid = threadIdx.x;              // 512 threads, 1 block
    __shared__ int sh[512];
    int orig = (tid < SCAN_NB) ? g_scanblk[tid] : 0;
    sh[tid] = orig; __syncthreads();
    for (int off = 1; off < 512; off <<= 1) {
        int add = (tid >= off) ? sh[tid - off] : 0;
        __syncthreads();
        sh[tid] += add;
        __syncthreads();
    }
    if (tid < SCAN_NB) g_scanblk[tid] = sh[tid] - orig;   // exclusive
}

__global__ void k_scanC() {
    int b = blockIdx.x, tid = threadIdx.x;
    int base = b * SCAN_CHUNK + tid * 16;
    int v[16];
    #pragma unroll
    for (int j = 0; j < 16; j++) {
        int idx = base + j;
        v[j] = (idx < KEYN) ? g_keycnt[idx] : 0;
    }
    int tot = 0;
    #pragma unroll
    for (int j = 0; j < 16; j++) { int t = v[j]; v[j] = tot; tot += t; }
    __shared__ int sh[256];
    sh[tid] = tot; __syncthreads();
    int orig = tot;
    for (int off = 1; off < 256; off <<= 1) {
        int add = (tid >= off) ? sh[tid - off] : 0;
        __syncthreads();
        sh[tid] += add;
        __syncthreads();
    }
    int texcl = sh[tid] - orig + g_scanblk[b];
    #pragma unroll
    for (int j = 0; j < 16; j++) {
        int idx = base + j;
        if (idx < KEYN) g_keyoff[idx] = texcl + v[j];
    }
}

// ---------------------------------------------------------------------------
// Scatter: after this, g_keyoff[k] = exclusive END of key k
// ---------------------------------------------------------------------------
__global__ void k_scatter(const int* __restrict__ triples) {
    int idx = blockIdx.x * blockDim.x + threadIdx.x;
    if (idx >= ETOT) return;
    int src, p, o;
    decode_edge(idx, triples, src, p, o);
    int pos = atomicAdd(&g_keyoff[src * R2 + p], 1);
    g_sorted[pos] = (p << 16) | o;
}

// ---------------------------------------------------------------------------
// Layer 1: 16-thread group per node, register accumulation, no atomics.
// ---------------------------------------------------------------------------
__global__ void k_layer1(const float* __restrict__ w0, const float* __restrict__ b0) {
    int t = blockIdx.x * blockDim.x + threadIdx.x;
    int u = t >> 4, lane = t & 15;
    if (u >= N_NODES) return;
    int s = (u == 0) ? 0 : g_keyoff[u * R2 - 1];
    int e = g_keyoff[u * R2 + R2 - 1];

    const float4* w0f4 = reinterpret_cast<const float4*>(w0);
    float4 acc = make_float4(0.f, 0.f, 0.f, 0.f);
    for (int i = s; i < e; i++) {
        int packed = g_sorted[i];
        int p = packed >> 16, o = packed & 0xFFFF;
        int col = p * N_NODES + o;
        float val = 1.0f / (float)g_colsum[col];
        float4 w = __ldg(w0f4 + (size_t)col * 16 + lane);
        acc.x = fmaf(val, w.x, acc.x);
        acc.y = fmaf(val, w.y, acc.y);
        acc.z = fmaf(val, w.z, acc.z);
        acc.w = fmaf(val, w.w, acc.w);
    }
    float4 bb = __ldg(reinterpret_cast<const float4*>(b0) + lane);
    float4 r = make_float4(bb.x + acc.x, bb.y + acc.y, bb.z + acc.z, bb.w + acc.w);
    *reinterpret_cast<float4*>(g_h + u * 64 + lane * 4) = r;
}

// ---------------------------------------------------------------------------
__global__ void k_flag(const int* __restrict__ batch) {
    int b = blockIdx.x * blockDim.x + threadIdx.x;
    if (b < BATCH) {
        g_flag[batch[3 * b + 0]] = 1;
        g_flag[batch[3 * b + 2]] = 1;
    }
}

__global__ void k_compact() {
    int u = blockIdx.x * blockDim.x + threadIdx.x;
    if (u < N_NODES && g_flag[u]) {
        int i = atomicAdd(&g_cnt[0], 1);
        g_list[i] = u;
    }
}

// ---------------------------------------------------------------------------
// Layer 2: one warp per flagged node (round-7 structure). Per p-run,
// accumulate hsum (float2 over cols — k-contiguous in shared), then flush
// with FFMA2 against the interleaved w1 (coalesced LDG.128, 4 lines/req).
// Accumulator = packed column pair (2l, 2l+1).
// Flush: 1 STS.64 + 16 LDS.128 + 32 LDG.128 + 64 FFMA2 (+64 ALU dups).
// ---------------------------------------------------------------------------
__global__ void k_layer2(const float* __restrict__ b1) {
    int t = blockIdx.x * blockDim.x + threadIdx.x;
    int w = t >> 5, lane = t & 31;
    int wid = threadIdx.x >> 5;
    __shared__ __align__(16) float hs[8][64];

    if (w >= g_cnt[0]) return;
    int u = g_list[w];

    int s = (u == 0) ? 0 : g_keyoff[u * R2 - 1];
    int e = g_keyoff[u * R2 + R2 - 1];

    unsigned long long acc = 0ull;          // (col 2*lane, col 2*lane+1)
    float2 hacc = make_float2(0.f, 0.f);
    int curp = -1;

    for (int i = s; i <= e; i++) {
        int p = -2, o = 0;
        if (i < e) {
            int pk = g_sorted[i];
            p = pk >> 16; o = pk & 0xFFFF;
        }
        if (p != curp) {
            if (curp >= 0) {
                *reinterpret_cast<float2*>(&hs[wid][2 * lane]) = hacc;  // k-order
                __syncwarp();
                const ulonglong2* W = g_w1i + curp * 1024 + lane;       // stride 32/k2
                const float4* H = reinterpret_cast<const float4*>(hs[wid]);
                #pragma unroll
                for (int j = 0; j < 16; j++) {
                    float4 h4 = H[j];                   // h[4j..4j+3]
                    ulonglong2 w01 = __ldg(W + (2 * j) * 32);       // k = 4j, 4j+1
                    ffma2(acc, dup2(h4.x), w01.x);
                    ffma2(acc, dup2(h4.y), w01.y);
                    ulonglong2 w23 = __ldg(W + (2 * j + 1) * 32);   // k = 4j+2, 4j+3
                    ffma2(acc, dup2(h4.z), w23.x);
                    ffma2(acc, dup2(h4.w), w23.y);
                }
                __syncwarp();
            }
            curp = p;
            hacc = make_float2(0.f, 0.f);
        }
        if (i < e) {
            float val = 1.0f / (float)g_colsum[p * N_NODES + o];
            float2 hv = *reinterpret_cast<const float2*>(g_h + o * 64 + 2 * lane);
            hacc.x = fmaf(val, hv.x, hacc.x);
            hacc.y = fmaf(val, hv.y, hacc.y);
        }
    }

    float c0, c1;
    unpack2(c0, c1, acc);
    float2 bb = *reinterpret_cast<const float2*>(b1 + 2 * lane);
    float2 r = make_float2(bb.x + c0, bb.y + c1);
    *reinterpret_cast<float2*>(g_nodes + u * 64 + 2 * lane) = r;
}

// ---------------------------------------------------------------------------
__global__ void k_score(const int* __restrict__ batch, const float* __restrict__ rel,
                        float* __restrict__ out) {
    int t = blockIdx.x * blockDim.x + threadIdx.x;
    int b = t >> 5, lane = t & 31;
    if (b >= BATCH) return;
    int si = batch[3 * b + 0];
    int pi = batch[3 * b + 1];
    int oi = batch[3 * b + 2];
    const float* ns = g_nodes + si * 64;
    const float* no = g_nodes + oi * 64;
    const float* rr = rel + pi * 64;
    float a = ns[lane]      * rr[lane]      * no[lane]
            + ns[lane + 32] * rr[lane + 32] * no[lane + 32];
    #pragma unroll
    for (int off = 16; off; off >>= 1)
        a += __shfl_xor_sync(0xffffffffu, a, off);
    if (lane == 0) out[b] = a;
}

// ---------------------------------------------------------------------------
extern "C" void kernel_launch(void* const* d_in, const int* in_sizes, int n_in,
                              void* d_out, int out_size) {
    const int*   batch     = (const int*)  d_in[0];
    const int*   triples   = (const int*)  d_in[1];
    const float* w0        = (const float*)d_in[2];
    const float* b0        = (const float*)d_in[3];
    const float* w1        = (const float*)d_in[4];
    const float* b1        = (const float*)d_in[5];
    const float* relations = (const float*)d_in[6];
    float* out = (float*)d_out;

    const int TPB = 256;

    k_init<<<(KEYN + TPB - 1) / TPB, TPB>>>();
    k_w1i<<<(R2 * 32 * 32 + TPB - 1) / TPB, TPB>>>(w1);
    k_hist<<<(ETOT + TPB - 1) / TPB, TPB>>>(triples);
    k_scanA<<<SCAN_NB, 256>>>();
    k_scanB<<<1, 512>>>();
    k_scanC<<<SCAN_NB, 256>>>();
    k_scatter<<<(ETOT + TPB - 1) / TPB, TPB>>>(triples);
    k_layer1<<<(N_NODES * 16 + TPB - 1) / TPB, TPB>>>(w0, b0);
    k_flag<<<(BATCH + TPB - 1) / TPB, TPB>>>(batch);
    k_compact<<<(N_NODES + TPB - 1) / TPB, TPB>>>();
    k_layer2<<<(MAXFLAG * 32 + TPB - 1) / TPB, TPB>>>(b1);
    k_score<<<(BATCH * 32 + TPB - 1) / TPB, TPB>>>(batch, relations, out);
}